// round 15
// baseline (speedup 1.0000x reference)
#include <cuda_runtime.h>
#include <cuda_bf16.h>
#include <math.h>

// ----------------------------------------------------------------------------
// GraphSAGE (3 layers) + up-proj + FUSED tri-pooling + MLP head. 7 launches.
// R14 structure with TILE 128->64 (8 blocks/SM, ~2x occupancy on sage kernels)
// and 4-deep-unrolled gather (MLP 4). h4 never materialized.
// N=100000, E=1600000, G=256, H=32, UP=128, out 51.
// Replay-safe: g_aggcnt / g_gsum / g_gmax reset by k_head tail.
// ----------------------------------------------------------------------------

#define MAXN 100000
#define MAXE 1600000
#define MAXG 256
#define TILE 64
#define SROW 36     // padded smem row stride (multiple of 4 for float4 align)
#define FENC_NEG_INF 0x007FFFFFu

__device__ int      g_csr[MAXE];
__device__ float2   g_aggcnt[MAXN];     // (.x = sum x[src], .y = in-degree) pre-zeroed
__device__ int      g_rowptr[MAXN + 1];
__device__ int      g_cursor[MAXN];
__device__ float    g_h1[MAXN * 32];    // h1, later reused for h3
__device__ float    g_h2[MAXN * 32];
__device__ int      g_start[MAXG + 1];
__device__ float    g_gsum[MAXG * 128]; // per-graph channel sums (pre-zeroed)
__device__ unsigned g_gmax[MAXG * 128]; // encoded per-graph maxima (pre-zeroed)

__device__ __forceinline__ float lrelu(float v) { return v > 0.f ? v : 0.01f * v; }
__device__ __forceinline__ float4 lrelu4(float4 v) {
    return make_float4(lrelu(v.x), lrelu(v.y), lrelu(v.z), lrelu(v.w));
}

// Order-preserving float<->uint encoding for atomicMax.
__device__ __forceinline__ unsigned fenc(float f) {
    unsigned b = __float_as_uint(f);
    return (b & 0x80000000u) ? ~b : (b | 0x80000000u);
}
__device__ __forceinline__ float fdec(unsigned u) {
    return (u & 0x80000000u) ? __uint_as_float(u & 0x7FFFFFFFu)
                             : __uint_as_float(~u);
}

// Per-block dtype sniff: int64 little-endian small nonneg => odd words zero.
__device__ __forceinline__ int sniff64(const unsigned* w, int base) {
    int lane = threadIdx.x & 31;
    unsigned v = w[base + 2 * lane + 1];
    unsigned nz = __ballot_sync(0xffffffffu, v != 0u);
    return nz == 0u;
}

// ---------------------------------------------------------------------------
// 1) Histogram + layer-1 scalar scatter fused into ONE v2 float RED per edge.
// ---------------------------------------------------------------------------
__global__ void k_hist(const float* __restrict__ x, const void* __restrict__ eidx,
                       int E) {
    __shared__ int se64;
    if (threadIdx.x < 32) {
        int f = sniff64((const unsigned*)eidx, 0);
        if (threadIdx.x == 0) se64 = f;
    }
    __syncthreads();
    int i = blockIdx.x * blockDim.x + threadIdx.x;
    if (i >= E) return;
    int s, d;
    if (se64) {
        const long long* p = (const long long*)eidx;
        s = (int)p[i];
        d = (int)p[(size_t)E + i];
    } else {
        const int* p = (const int*)eidx;
        s = p[i];
        d = p[E + i];
    }
    float xv = __ldg(&x[s]);
    float* addr = (float*)&g_aggcnt[d];
    asm volatile("red.global.add.v2.f32 [%0], {%1,%2};"
                 :: "l"(addr), "f"(xv), "f"(1.0f) : "memory");
}

// ---------------------------------------------------------------------------
// 2) Scan + starts in one launch. Block 0: single-block chunked exclusive scan
//    of in-degrees -> g_rowptr/g_cursor. Blocks >= 1: per-graph start offsets.
// ---------------------------------------------------------------------------
__global__ void k_scan_starts(const void* __restrict__ batch,
                              int N, int E, int G, int bbase) {
    if (blockIdx.x == 0) {
        __shared__ int ssum[1024];
        int t = threadIdx.x;
        int chunk = (N + 1023) / 1024;
        int a = t * chunk;
        int b = min(N, a + chunk);
        int s = 0;
        for (int i = a; i < b; i++) s += (int)g_aggcnt[i].y;
        ssum[t] = s;
        __syncthreads();
        for (int off = 1; off < 1024; off <<= 1) {
            int u = (t >= off) ? ssum[t - off] : 0;
            __syncthreads();
            ssum[t] += u;
            __syncthreads();
        }
        int run = ssum[t] - s;
        for (int i = a; i < b; i++) {
            g_rowptr[i] = run;
            g_cursor[i] = run;
            run += (int)g_aggcnt[i].y;
        }
        if (t == 1023) g_rowptr[N] = E;
    } else {
        __shared__ int sb64;
        if (threadIdx.x < 32) {
            int f = sniff64((const unsigned*)batch, bbase);
            if (threadIdx.x == 0) sb64 = f;
        }
        __syncthreads();
        int i = (blockIdx.x - 1) * blockDim.x + threadIdx.x;
        if (i >= N) return;
        long long bi, bp;
        if (sb64) {
            const long long* p = (const long long*)batch;
            bi = p[i]; bp = (i == 0) ? -1LL : p[i - 1];
        } else {
            const int* p = (const int*)batch;
            bi = p[i]; bp = (i == 0) ? -1LL : p[i - 1];
        }
        if (bi != bp) for (long long g = bp + 1; g <= bi; g++) g_start[g] = i;
        if (i == N - 1) for (long long g = bi + 1; g <= G; g++) g_start[g] = N;
    }
}

// ---------------------------------------------------------------------------
// 3) CSR fill + fused layer-1 transform (independent work ranges).
// ---------------------------------------------------------------------------
__global__ void k_csrfill_l1(const void* __restrict__ eidx, const float* __restrict__ x,
                             const float* __restrict__ W1l, const float* __restrict__ b1,
                             const float* __restrict__ W1r, int E, int N) {
    __shared__ int se64;
    if (threadIdx.x < 32) {
        int f = sniff64((const unsigned*)eidx, 0);
        if (threadIdx.x == 0) se64 = f;
    }
    __syncthreads();
    int i = blockIdx.x * blockDim.x + threadIdx.x;
    if (i < E) {
        int s, d;
        if (se64) {
            const long long* p = (const long long*)eidx;
            s = (int)p[i];
            d = (int)p[(size_t)E + i];
        } else {
            const int* p = (const int*)eidx;
            s = p[i];
            d = p[E + i];
        }
        int pos = atomicAdd(&g_cursor[d], 1);
        g_csr[pos] = s;
    }
    if (i < N * 8) {
        int node = i >> 3, q = i & 7;
        float a  = __ldg(&((const float*)g_aggcnt)[node * 2]);
        float xv = __ldg(&x[node]);
        float4 wl = __ldg(&((const float4*)W1l)[q]);
        float4 wr = __ldg(&((const float4*)W1r)[q]);
        float4 bb = __ldg(&((const float4*)b1)[q]);
        float4 o;
        o.x = lrelu(a * wl.x + xv * wr.x + bb.x);
        o.y = lrelu(a * wl.y + xv * wr.y + bb.y);
        o.z = lrelu(a * wl.z + xv * wr.z + bb.z);
        o.w = lrelu(a * wl.w + xv * wr.w + bb.w);
        ((float4*)g_h1)[node * 8 + q] = o;
    }
}

// ---------------------------------------------------------------------------
// Gather helper: warp gathers 32-ch sum into float4 (quad q). 4 edge slots x
// 4-deep unroll => up to 4 independent (csr, h) load pairs in flight (MLP 4).
// ---------------------------------------------------------------------------
__device__ __forceinline__ float4 gather_f4(const float4* __restrict__ hf4,
                                            int s0, int s1, int slot, int q) {
    float4 a0 = make_float4(0.f, 0.f, 0.f, 0.f);
    float4 a1 = a0, a2 = a0, a3 = a0;
    int e = s0 + slot;
    for (; e + 12 < s1; e += 16) {
        int i0 = __ldg(&g_csr[e]);
        int i1 = __ldg(&g_csr[e + 4]);
        int i2 = __ldg(&g_csr[e + 8]);
        int i3 = __ldg(&g_csr[e + 12]);
        float4 v0 = __ldg(&hf4[i0 * 8 + q]);
        float4 v1 = __ldg(&hf4[i1 * 8 + q]);
        float4 v2 = __ldg(&hf4[i2 * 8 + q]);
        float4 v3 = __ldg(&hf4[i3 * 8 + q]);
        a0.x += v0.x; a0.y += v0.y; a0.z += v0.z; a0.w += v0.w;
        a1.x += v1.x; a1.y += v1.y; a1.z += v1.z; a1.w += v1.w;
        a2.x += v2.x; a2.y += v2.y; a2.z += v2.z; a2.w += v2.w;
        a3.x += v3.x; a3.y += v3.y; a3.z += v3.z; a3.w += v3.w;
    }
    for (; e < s1; e += 4) {
        int i0 = __ldg(&g_csr[e]);
        float4 v0 = __ldg(&hf4[i0 * 8 + q]);
        a0.x += v0.x; a0.y += v0.y; a0.z += v0.z; a0.w += v0.w;
    }
    float4 acc;
    acc.x = (a0.x + a1.x) + (a2.x + a3.x);
    acc.y = (a0.y + a1.y) + (a2.y + a3.y);
    acc.z = (a0.z + a1.z) + (a2.z + a3.z);
    acc.w = (a0.w + a1.w) + (a2.w + a3.w);
    #pragma unroll
    for (int off = 8; off <= 16; off <<= 1) {
        acc.x += __shfl_xor_sync(0xffffffffu, acc.x, off);
        acc.y += __shfl_xor_sync(0xffffffffu, acc.y, off);
        acc.z += __shfl_xor_sync(0xffffffffu, acc.z, off);
        acc.w += __shfl_xor_sync(0xffffffffu, acc.w, off);
    }
    return acc;
}

// ---------------------------------------------------------------------------
// 4) Layer 2: tile of 64 nodes, gather -> smem, tiled GEMM, 8 blocks/SM.
//    GEMM stage: 2 nodes x 4 channels per thread.
// ---------------------------------------------------------------------------
__global__ __launch_bounds__(256, 8)
void k_sage2(const float* __restrict__ Wl, const float* __restrict__ b,
             const float* __restrict__ Wr, int N) {
    __shared__ float sA[TILE * SROW], sH[TILE * SROW];
    __shared__ float4 sWl4[256], sWr4[256], sb4[8];
    if (threadIdx.x < 256) {
        sWl4[threadIdx.x] = __ldg(&((const float4*)Wl)[threadIdx.x]);
        sWr4[threadIdx.x] = __ldg(&((const float4*)Wr)[threadIdx.x]);
    }
    if (threadIdx.x < 8) sb4[threadIdx.x] = __ldg(&((const float4*)b)[threadIdx.x]);

    int lane = threadIdx.x & 31, w = threadIdx.x >> 5;
    int slot = lane >> 3, q = lane & 7;
    int base = blockIdx.x * TILE;
    const float4* h1f4 = (const float4*)g_h1;

    for (int r = 0; r < TILE / 8; r++) {
        int local = w * (TILE / 8) + r;
        int node = base + local;
        if (node >= N) break;
        int s0 = __ldg(&g_rowptr[node]), s1 = __ldg(&g_rowptr[node + 1]);
        float4 agg = gather_f4(h1f4, s0, s1, slot, q);
        if (slot == 0) {
            *(float4*)&sA[local * SROW + q * 4] = agg;
            *(float4*)&sH[local * SROW + q * 4] = __ldg(&h1f4[node * 8 + q]);
        }
    }
    __syncthreads();

    // 256 threads = 8 quads x 32 groups; group owns 2 nodes.
    int tq = threadIdx.x & 7, tg = threadIdx.x >> 3;
    int n0 = tg * 2;
    float4 c0 = sb4[tq], c1 = c0;
    #pragma unroll 8
    for (int k = 0; k < 32; k++) {
        float4 wl = sWl4[k * 8 + tq];
        float4 wr = sWr4[k * 8 + tq];
        float a0 = sA[(n0 + 0) * SROW + k], h0 = sH[(n0 + 0) * SROW + k];
        float a1 = sA[(n0 + 1) * SROW + k], h1 = sH[(n0 + 1) * SROW + k];
        c0.x += a0 * wl.x + h0 * wr.x; c0.y += a0 * wl.y + h0 * wr.y;
        c0.z += a0 * wl.z + h0 * wr.z; c0.w += a0 * wl.w + h0 * wr.w;
        c1.x += a1 * wl.x + h1 * wr.x; c1.y += a1 * wl.y + h1 * wr.y;
        c1.z += a1 * wl.z + h1 * wr.z; c1.w += a1 * wl.w + h1 * wr.w;
    }
    float4* h2f4 = (float4*)g_h2;
    int nb = base + n0;
    if (nb + 0 < N) h2f4[(nb + 0) * 8 + tq] = lrelu4(c0);
    if (nb + 1 < N) h2f4[(nb + 1) * 8 + tq] = lrelu4(c1);
}

// ---------------------------------------------------------------------------
// 5) Layer 3 (mean aggr): same tiled body; writes h3 into g_h1 (h1 is dead).
// ---------------------------------------------------------------------------
__global__ __launch_bounds__(256, 8)
void k_sage3(const float* __restrict__ Wl, const float* __restrict__ b,
             const float* __restrict__ Wr, int N) {
    __shared__ float sA[TILE * SROW], sH[TILE * SROW];
    __shared__ float4 sWl4[256], sWr4[256], sb4[8];
    if (threadIdx.x < 256) {
        sWl4[threadIdx.x] = __ldg(&((const float4*)Wl)[threadIdx.x]);
        sWr4[threadIdx.x] = __ldg(&((const float4*)Wr)[threadIdx.x]);
    }
    if (threadIdx.x < 8) sb4[threadIdx.x] = __ldg(&((const float4*)b)[threadIdx.x]);

    int lane = threadIdx.x & 31, w = threadIdx.x >> 5;
    int slot = lane >> 3, q = lane & 7;
    int base = blockIdx.x * TILE;
    const float4* h2f4 = (const float4*)g_h2;

    for (int r = 0; r < TILE / 8; r++) {
        int local = w * (TILE / 8) + r;
        int node = base + local;
        if (node >= N) break;
        int s0 = __ldg(&g_rowptr[node]), s1 = __ldg(&g_rowptr[node + 1]);
        float4 agg = gather_f4(h2f4, s0, s1, slot, q);
        if (slot == 0) {
            float inv = 1.0f / fmaxf((float)(s1 - s0), 1.0f);
            agg.x *= inv; agg.y *= inv; agg.z *= inv; agg.w *= inv;
            *(float4*)&sA[local * SROW + q * 4] = agg;
            *(float4*)&sH[local * SROW + q * 4] = __ldg(&h2f4[node * 8 + q]);
        }
    }
    __syncthreads();

    int tq = threadIdx.x & 7, tg = threadIdx.x >> 3;
    int n0 = tg * 2;
    float4 c0 = sb4[tq], c1 = c0;
    #pragma unroll 8
    for (int k = 0; k < 32; k++) {
        float4 wl = sWl4[k * 8 + tq];
        float4 wr = sWr4[k * 8 + tq];
        float a0 = sA[(n0 + 0) * SROW + k], h0 = sH[(n0 + 0) * SROW + k];
        float a1 = sA[(n0 + 1) * SROW + k], h1 = sH[(n0 + 1) * SROW + k];
        c0.x += a0 * wl.x + h0 * wr.x; c0.y += a0 * wl.y + h0 * wr.y;
        c0.z += a0 * wl.z + h0 * wr.z; c0.w += a0 * wl.w + h0 * wr.w;
        c1.x += a1 * wl.x + h1 * wr.x; c1.y += a1 * wl.y + h1 * wr.y;
        c1.z += a1 * wl.z + h1 * wr.z; c1.w += a1 * wl.w + h1 * wr.w;
    }
    float4* h3f4 = (float4*)g_h1;   // reuse h1 buffer for h3
    int nb = base + n0;
    if (nb + 0 < N) h3f4[(nb + 0) * 8 + tq] = lrelu4(c0);
    if (nb + 1 < N) h3f4[(nb + 1) * 8 + tq] = lrelu4(c1);
}

// ---------------------------------------------------------------------------
// 6) Dense up-projection + FUSED tri-pooling. Tile of 64 contiguous nodes.
//    2 passes x (8 groups x 4 nodes); register pool accumulators flushed at
//    graph boundaries (batch sorted). h4 never hits DRAM.
// ---------------------------------------------------------------------------
#define SROW3 36
__device__ __forceinline__ void flush_pool4(int g, int cbase, float4 ps, float4 pm) {
    if (g < 0) return;
    float* sp = g_gsum + g * 128 + cbase;
    unsigned* mp = g_gmax + g * 128 + cbase;
    atomicAdd(sp + 0, ps.x); atomicAdd(sp + 1, ps.y);
    atomicAdd(sp + 2, ps.z); atomicAdd(sp + 3, ps.w);
    atomicMax(mp + 0, fenc(pm.x)); atomicMax(mp + 1, fenc(pm.y));
    atomicMax(mp + 2, fenc(pm.z)); atomicMax(mp + 3, fenc(pm.w));
}

__global__ __launch_bounds__(256, 8)
void k_upproj_pool(const float* __restrict__ Wu, const float* __restrict__ bu,
                   const void* __restrict__ batch, int N, int bbase) {
    __shared__ float sh3[TILE * SROW3];
    __shared__ float4 sWu4[1024];       // Wu [32][128] = 16 KB
    __shared__ float4 sbu4[32];
    __shared__ int sb64;
    for (int i = threadIdx.x; i < 1024; i += 256)
        sWu4[i] = __ldg(&((const float4*)Wu)[i]);
    if (threadIdx.x < 32) {
        sbu4[threadIdx.x] = __ldg(&((const float4*)bu)[threadIdx.x]);
        int f = sniff64((const unsigned*)batch, bbase);
        if (threadIdx.x == 0) sb64 = f;
    }

    int base = blockIdx.x * TILE;
    const float4* h3f4 = (const float4*)g_h1;
    for (int i = threadIdx.x; i < TILE * 8; i += 256) {
        int local = i >> 3, q = i & 7;
        int node = base + local;
        int nc = (node < N) ? node : (N - 1);
        *(float4*)&sh3[local * SROW3 + q * 4] = __ldg(&h3f4[nc * 8 + q]);
    }
    __syncthreads();
    int e64 = sb64;

    int oq = threadIdx.x & 31, g8 = threadIdx.x >> 5;
    int cbase = oq * 4;
    int gcur = -1;
    float4 psum = make_float4(0.f, 0.f, 0.f, 0.f);
    float4 pmax = make_float4(-INFINITY, -INFINITY, -INFINITY, -INFINITY);

    #pragma unroll
    for (int pass = 0; pass < 2; pass++) {
        int nb = pass * 32 + g8 * 4;
        float4 u0 = sbu4[oq], u1 = u0, u2 = u0, u3 = u0;
        #pragma unroll 4
        for (int k = 0; k < 32; k++) {
            float4 wv = sWu4[k * 32 + oq];
            float p0 = sh3[(nb + 0) * SROW3 + k];
            float p1 = sh3[(nb + 1) * SROW3 + k];
            float p2 = sh3[(nb + 2) * SROW3 + k];
            float p3 = sh3[(nb + 3) * SROW3 + k];
            u0.x += p0 * wv.x; u0.y += p0 * wv.y; u0.z += p0 * wv.z; u0.w += p0 * wv.w;
            u1.x += p1 * wv.x; u1.y += p1 * wv.y; u1.z += p1 * wv.z; u1.w += p1 * wv.w;
            u2.x += p2 * wv.x; u2.y += p2 * wv.y; u2.z += p2 * wv.z; u2.w += p2 * wv.w;
            u3.x += p3 * wv.x; u3.y += p3 * wv.y; u3.z += p3 * wv.z; u3.w += p3 * wv.w;
        }
        float4 hu[4] = { lrelu4(u0), lrelu4(u1), lrelu4(u2), lrelu4(u3) };
        #pragma unroll
        for (int j = 0; j < 4; j++) {
            int node = base + nb + j;
            if (node >= N) break;
            int gid = e64 ? (int)((const long long*)batch)[node]
                          : ((const int*)batch)[node];
            if (gid != gcur) {
                flush_pool4(gcur, cbase, psum, pmax);
                gcur = gid;
                psum = make_float4(0.f, 0.f, 0.f, 0.f);
                pmax = make_float4(-INFINITY, -INFINITY, -INFINITY, -INFINITY);
            }
            float4 v = hu[j];
            psum.x += v.x; psum.y += v.y; psum.z += v.z; psum.w += v.w;
            pmax.x = fmaxf(pmax.x, v.x); pmax.y = fmaxf(pmax.y, v.y);
            pmax.z = fmaxf(pmax.z, v.z); pmax.w = fmaxf(pmax.w, v.w);
        }
    }
    flush_pool4(gcur, cbase, psum, pmax);
}

// ---------------------------------------------------------------------------
// 7) Head + replay-state reset.
// ---------------------------------------------------------------------------
__global__ void k_head(const float* __restrict__ Wf1, const float* __restrict__ bf1,
                       const float* __restrict__ Wf2, const float* __restrict__ bf2,
                       float* __restrict__ out, int N, int G) {
    __shared__ float sz[384], sz2[128];
    int g = blockIdx.x;
    int c = threadIdx.x;   // 128 threads
    float sum = g_gsum[g * 128 + c];
    float mx  = fdec(g_gmax[g * 128 + c]);
    float cnt = (float)(g_start[g + 1] - g_start[g]);
    sz[c]       = sum / fmaxf(cnt, 1.0f);
    sz[128 + c] = mx;
    sz[256 + c] = sum;
    __syncthreads();
    // Replay-state reset (none of these are read by k_head after this point).
    g_gsum[g * 128 + c] = 0.f;
    g_gmax[g * 128 + c] = FENC_NEG_INF;
    for (int i = g * 128 + c; i < N; i += G * 128) g_aggcnt[i] = make_float2(0.f, 0.f);

    float acc = bf1[c];
    #pragma unroll 4
    for (int k = 0; k < 384; k++) acc += sz[k] * Wf1[k * 128 + c];
    sz2[c] = lrelu(acc);
    __syncthreads();
    if (c < 51) {
        float o = bf2[c];
        #pragma unroll 4
        for (int k = 0; k < 128; k++) o += sz2[k] * Wf2[k * 51 + c];
        out[g * 51 + c] = o;
    }
}

// ---------------------------------------------------------------------------
extern "C" void kernel_launch(void* const* d_in, const int* in_sizes, int n_in,
                              void* d_out, int out_size) {
    const float* x    = (const float*)d_in[0];
    const void*  eidx = d_in[1];
    const void*  batch= d_in[2];
    const float* W1l  = (const float*)d_in[3];
    const float* b1   = (const float*)d_in[4];
    const float* W1r  = (const float*)d_in[5];
    const float* W2l  = (const float*)d_in[6];
    const float* b2   = (const float*)d_in[7];
    const float* W2r  = (const float*)d_in[8];
    const float* W3l  = (const float*)d_in[9];
    const float* b3   = (const float*)d_in[10];
    const float* W3r  = (const float*)d_in[11];
    const float* Wu   = (const float*)d_in[12];
    const float* bu   = (const float*)d_in[13];
    const float* Wf1  = (const float*)d_in[14];
    const float* bf1  = (const float*)d_in[15];
    const float* Wf2  = (const float*)d_in[16];
    const float* bf2  = (const float*)d_in[17];
    float* out = (float*)d_out;

    int N = in_sizes[0];
    int E = in_sizes[1] / 2;
    int G = out_size / 51;
    int bbase = (N - 64) & ~1;

    int fill_threads = (E > N * 8) ? E : N * 8;
    int tile_blocks = (N + TILE - 1) / TILE;
    int starts_blocks = 1 + (N + 1023) / 1024;

    k_hist<<<(E + 255) / 256, 256>>>(x, eidx, E);
    k_scan_starts<<<starts_blocks, 1024>>>(batch, N, E, G, bbase);
    k_csrfill_l1<<<(fill_threads + 255) / 256, 256>>>(eidx, x, W1l, b1, W1r, E, N);
    k_sage2<<<tile_blocks, 256>>>(W2l, b2, W2r, N);        // <- profiled launch #4
    k_sage3<<<tile_blocks, 256>>>(W3l, b3, W3r, N);
    k_upproj_pool<<<tile_blocks, 256>>>(Wu, bu, batch, N, bbase);
    k_head<<<G, 128>>>(Wf1, bf1, Wf2, bf2, out, N, G);
}

// round 16
// speedup vs baseline: 1.3061x; 1.3061x over previous
#include <cuda_runtime.h>
#include <cuda_bf16.h>
#include <math.h>

// ----------------------------------------------------------------------------
// GraphSAGE (3 layers) + up-proj + FUSED tri-pooling + MLP head. 7 launches.
// R14 structure (TILE 128, occ 4, measured-best) with ONE change: gather
// unrolled 4-deep (MLP 4) instead of 2-deep. h4 never materialized.
// N=100000, E=1600000, G=256, H=32, UP=128, out 51.
// Replay-safe: g_aggcnt / g_gsum / g_gmax reset by k_head tail.
// ----------------------------------------------------------------------------

#define MAXN 100000
#define MAXE 1600000
#define MAXG 256
#define TILE 128
#define SROW 36     // padded smem row stride (multiple of 4 for float4 align)
#define FENC_NEG_INF 0x007FFFFFu

__device__ int      g_csr[MAXE];
__device__ float2   g_aggcnt[MAXN];     // (.x = sum x[src], .y = in-degree) pre-zeroed
__device__ int      g_rowptr[MAXN + 1];
__device__ int      g_cursor[MAXN];
__device__ float    g_h1[MAXN * 32];    // h1, later reused for h3
__device__ float    g_h2[MAXN * 32];
__device__ int      g_start[MAXG + 1];
__device__ float    g_gsum[MAXG * 128]; // per-graph channel sums (pre-zeroed)
__device__ unsigned g_gmax[MAXG * 128]; // encoded per-graph maxima (pre-zeroed)

__device__ __forceinline__ float lrelu(float v) { return v > 0.f ? v : 0.01f * v; }
__device__ __forceinline__ float4 lrelu4(float4 v) {
    return make_float4(lrelu(v.x), lrelu(v.y), lrelu(v.z), lrelu(v.w));
}

// Order-preserving float<->uint encoding for atomicMax.
__device__ __forceinline__ unsigned fenc(float f) {
    unsigned b = __float_as_uint(f);
    return (b & 0x80000000u) ? ~b : (b | 0x80000000u);
}
__device__ __forceinline__ float fdec(unsigned u) {
    return (u & 0x80000000u) ? __uint_as_float(u & 0x7FFFFFFFu)
                             : __uint_as_float(~u);
}

// Per-block dtype sniff: int64 little-endian small nonneg => odd words zero.
__device__ __forceinline__ int sniff64(const unsigned* w, int base) {
    int lane = threadIdx.x & 31;
    unsigned v = w[base + 2 * lane + 1];
    unsigned nz = __ballot_sync(0xffffffffu, v != 0u);
    return nz == 0u;
}

// ---------------------------------------------------------------------------
// 1) Histogram + layer-1 scalar scatter fused into ONE v2 float RED per edge.
// ---------------------------------------------------------------------------
__global__ void k_hist(const float* __restrict__ x, const void* __restrict__ eidx,
                       int E) {
    __shared__ int se64;
    if (threadIdx.x < 32) {
        int f = sniff64((const unsigned*)eidx, 0);
        if (threadIdx.x == 0) se64 = f;
    }
    __syncthreads();
    int i = blockIdx.x * blockDim.x + threadIdx.x;
    if (i >= E) return;
    int s, d;
    if (se64) {
        const long long* p = (const long long*)eidx;
        s = (int)p[i];
        d = (int)p[(size_t)E + i];
    } else {
        const int* p = (const int*)eidx;
        s = p[i];
        d = p[E + i];
    }
    float xv = __ldg(&x[s]);
    float* addr = (float*)&g_aggcnt[d];
    asm volatile("red.global.add.v2.f32 [%0], {%1,%2};"
                 :: "l"(addr), "f"(xv), "f"(1.0f) : "memory");
}

// ---------------------------------------------------------------------------
// 2) Scan + starts in one launch. Block 0: single-block chunked exclusive scan
//    of in-degrees -> g_rowptr/g_cursor. Blocks >= 1: per-graph start offsets.
// ---------------------------------------------------------------------------
__global__ void k_scan_starts(const void* __restrict__ batch,
                              int N, int E, int G, int bbase) {
    if (blockIdx.x == 0) {
        __shared__ int ssum[1024];
        int t = threadIdx.x;
        int chunk = (N + 1023) / 1024;
        int a = t * chunk;
        int b = min(N, a + chunk);
        int s = 0;
        for (int i = a; i < b; i++) s += (int)g_aggcnt[i].y;
        ssum[t] = s;
        __syncthreads();
        for (int off = 1; off < 1024; off <<= 1) {
            int u = (t >= off) ? ssum[t - off] : 0;
            __syncthreads();
            ssum[t] += u;
            __syncthreads();
        }
        int run = ssum[t] - s;
        for (int i = a; i < b; i++) {
            g_rowptr[i] = run;
            g_cursor[i] = run;
            run += (int)g_aggcnt[i].y;
        }
        if (t == 1023) g_rowptr[N] = E;
    } else {
        __shared__ int sb64;
        if (threadIdx.x < 32) {
            int f = sniff64((const unsigned*)batch, bbase);
            if (threadIdx.x == 0) sb64 = f;
        }
        __syncthreads();
        int i = (blockIdx.x - 1) * blockDim.x + threadIdx.x;
        if (i >= N) return;
        long long bi, bp;
        if (sb64) {
            const long long* p = (const long long*)batch;
            bi = p[i]; bp = (i == 0) ? -1LL : p[i - 1];
        } else {
            const int* p = (const int*)batch;
            bi = p[i]; bp = (i == 0) ? -1LL : p[i - 1];
        }
        if (bi != bp) for (long long g = bp + 1; g <= bi; g++) g_start[g] = i;
        if (i == N - 1) for (long long g = bi + 1; g <= G; g++) g_start[g] = N;
    }
}

// ---------------------------------------------------------------------------
// 3) CSR fill + fused layer-1 transform (independent work ranges).
// ---------------------------------------------------------------------------
__global__ void k_csrfill_l1(const void* __restrict__ eidx, const float* __restrict__ x,
                             const float* __restrict__ W1l, const float* __restrict__ b1,
                             const float* __restrict__ W1r, int E, int N) {
    __shared__ int se64;
    if (threadIdx.x < 32) {
        int f = sniff64((const unsigned*)eidx, 0);
        if (threadIdx.x == 0) se64 = f;
    }
    __syncthreads();
    int i = blockIdx.x * blockDim.x + threadIdx.x;
    if (i < E) {
        int s, d;
        if (se64) {
            const long long* p = (const long long*)eidx;
            s = (int)p[i];
            d = (int)p[(size_t)E + i];
        } else {
            const int* p = (const int*)eidx;
            s = p[i];
            d = p[E + i];
        }
        int pos = atomicAdd(&g_cursor[d], 1);
        g_csr[pos] = s;
    }
    if (i < N * 8) {
        int node = i >> 3, q = i & 7;
        float a  = __ldg(&((const float*)g_aggcnt)[node * 2]);
        float xv = __ldg(&x[node]);
        float4 wl = __ldg(&((const float4*)W1l)[q]);
        float4 wr = __ldg(&((const float4*)W1r)[q]);
        float4 bb = __ldg(&((const float4*)b1)[q]);
        float4 o;
        o.x = lrelu(a * wl.x + xv * wr.x + bb.x);
        o.y = lrelu(a * wl.y + xv * wr.y + bb.y);
        o.z = lrelu(a * wl.z + xv * wr.z + bb.z);
        o.w = lrelu(a * wl.w + xv * wr.w + bb.w);
        ((float4*)g_h1)[node * 8 + q] = o;
    }
}

// ---------------------------------------------------------------------------
// Gather helper: warp gathers 32-ch sum into float4 (quad q). 4 edge slots x
// 4-deep unroll => 4 independent (csr,row) pairs in flight per lane (MLP 4).
// ---------------------------------------------------------------------------
__device__ __forceinline__ float4 gather_f4(const float4* __restrict__ hf4,
                                            int s0, int s1, int slot, int q) {
    float4 a0 = make_float4(0.f, 0.f, 0.f, 0.f);
    float4 a1 = a0, a2 = a0, a3 = a0;
    int e = s0 + slot;
    for (; e + 12 < s1; e += 16) {
        int i0 = __ldg(&g_csr[e]);
        int i1 = __ldg(&g_csr[e + 4]);
        int i2 = __ldg(&g_csr[e + 8]);
        int i3 = __ldg(&g_csr[e + 12]);
        float4 v0 = __ldg(&hf4[i0 * 8 + q]);
        float4 v1 = __ldg(&hf4[i1 * 8 + q]);
        float4 v2 = __ldg(&hf4[i2 * 8 + q]);
        float4 v3 = __ldg(&hf4[i3 * 8 + q]);
        a0.x += v0.x; a0.y += v0.y; a0.z += v0.z; a0.w += v0.w;
        a1.x += v1.x; a1.y += v1.y; a1.z += v1.z; a1.w += v1.w;
        a2.x += v2.x; a2.y += v2.y; a2.z += v2.z; a2.w += v2.w;
        a3.x += v3.x; a3.y += v3.y; a3.z += v3.z; a3.w += v3.w;
    }
    for (; e < s1; e += 4) {
        int i0 = __ldg(&g_csr[e]);
        float4 v0 = __ldg(&hf4[i0 * 8 + q]);
        a0.x += v0.x; a0.y += v0.y; a0.z += v0.z; a0.w += v0.w;
    }
    float4 acc;
    acc.x = (a0.x + a1.x) + (a2.x + a3.x);
    acc.y = (a0.y + a1.y) + (a2.y + a3.y);
    acc.z = (a0.z + a1.z) + (a2.z + a3.z);
    acc.w = (a0.w + a1.w) + (a2.w + a3.w);
    #pragma unroll
    for (int off = 8; off <= 16; off <<= 1) {
        acc.x += __shfl_xor_sync(0xffffffffu, acc.x, off);
        acc.y += __shfl_xor_sync(0xffffffffu, acc.y, off);
        acc.z += __shfl_xor_sync(0xffffffffu, acc.z, off);
        acc.w += __shfl_xor_sync(0xffffffffu, acc.w, off);
    }
    return acc;
}

// ---------------------------------------------------------------------------
// 4) Layer 2: tile of 128 nodes, gather -> smem, tiled GEMM (measured body).
// ---------------------------------------------------------------------------
__global__ __launch_bounds__(256, 4)
void k_sage2(const float* __restrict__ Wl, const float* __restrict__ b,
             const float* __restrict__ Wr, int N) {
    __shared__ float sA[TILE * SROW], sH[TILE * SROW];
    __shared__ float4 sWl4[256], sWr4[256], sb4[8];
    if (threadIdx.x < 256) {
        sWl4[threadIdx.x] = __ldg(&((const float4*)Wl)[threadIdx.x]);
        sWr4[threadIdx.x] = __ldg(&((const float4*)Wr)[threadIdx.x]);
    }
    if (threadIdx.x < 8) sb4[threadIdx.x] = __ldg(&((const float4*)b)[threadIdx.x]);

    int lane = threadIdx.x & 31, w = threadIdx.x >> 5;
    int slot = lane >> 3, q = lane & 7;
    int base = blockIdx.x * TILE;
    const float4* h1f4 = (const float4*)g_h1;

    for (int r = 0; r < TILE / 8; r++) {
        int local = w * (TILE / 8) + r;
        int node = base + local;
        if (node >= N) break;
        int s0 = __ldg(&g_rowptr[node]), s1 = __ldg(&g_rowptr[node + 1]);
        float4 agg = gather_f4(h1f4, s0, s1, slot, q);
        if (slot == 0) {
            *(float4*)&sA[local * SROW + q * 4] = agg;
            *(float4*)&sH[local * SROW + q * 4] = __ldg(&h1f4[node * 8 + q]);
        }
    }
    __syncthreads();

    int tq = threadIdx.x & 7, tg = threadIdx.x >> 3;
    int n0 = tg * 4;
    float4 c0 = sb4[tq], c1 = c0, c2 = c0, c3 = c0;
    #pragma unroll 4
    for (int k = 0; k < 32; k++) {
        float4 wl = sWl4[k * 8 + tq];
        float4 wr = sWr4[k * 8 + tq];
        float a0 = sA[(n0 + 0) * SROW + k], h0 = sH[(n0 + 0) * SROW + k];
        float a1 = sA[(n0 + 1) * SROW + k], h1 = sH[(n0 + 1) * SROW + k];
        float a2 = sA[(n0 + 2) * SROW + k], h2 = sH[(n0 + 2) * SROW + k];
        float a3 = sA[(n0 + 3) * SROW + k], h3 = sH[(n0 + 3) * SROW + k];
        c0.x += a0 * wl.x + h0 * wr.x; c0.y += a0 * wl.y + h0 * wr.y;
        c0.z += a0 * wl.z + h0 * wr.z; c0.w += a0 * wl.w + h0 * wr.w;
        c1.x += a1 * wl.x + h1 * wr.x; c1.y += a1 * wl.y + h1 * wr.y;
        c1.z += a1 * wl.z + h1 * wr.z; c1.w += a1 * wl.w + h1 * wr.w;
        c2.x += a2 * wl.x + h2 * wr.x; c2.y += a2 * wl.y + h2 * wr.y;
        c2.z += a2 * wl.z + h2 * wr.z; c2.w += a2 * wl.w + h2 * wr.w;
        c3.x += a3 * wl.x + h3 * wr.x; c3.y += a3 * wl.y + h3 * wr.y;
        c3.z += a3 * wl.z + h3 * wr.z; c3.w += a3 * wl.w + h3 * wr.w;
    }
    float4* h2f4 = (float4*)g_h2;
    int nb = base + n0;
    if (nb + 0 < N) h2f4[(nb + 0) * 8 + tq] = lrelu4(c0);
    if (nb + 1 < N) h2f4[(nb + 1) * 8 + tq] = lrelu4(c1);
    if (nb + 2 < N) h2f4[(nb + 2) * 8 + tq] = lrelu4(c2);
    if (nb + 3 < N) h2f4[(nb + 3) * 8 + tq] = lrelu4(c3);
}

// ---------------------------------------------------------------------------
// 5) Layer 3 (mean aggr): same tiled body; writes h3 into g_h1 (h1 is dead).
// ---------------------------------------------------------------------------
__global__ __launch_bounds__(256, 4)
void k_sage3(const float* __restrict__ Wl, const float* __restrict__ b,
             const float* __restrict__ Wr, int N) {
    __shared__ float sA[TILE * SROW], sH[TILE * SROW];
    __shared__ float4 sWl4[256], sWr4[256], sb4[8];
    if (threadIdx.x < 256) {
        sWl4[threadIdx.x] = __ldg(&((const float4*)Wl)[threadIdx.x]);
        sWr4[threadIdx.x] = __ldg(&((const float4*)Wr)[threadIdx.x]);
    }
    if (threadIdx.x < 8) sb4[threadIdx.x] = __ldg(&((const float4*)b)[threadIdx.x]);

    int lane = threadIdx.x & 31, w = threadIdx.x >> 5;
    int slot = lane >> 3, q = lane & 7;
    int base = blockIdx.x * TILE;
    const float4* h2f4 = (const float4*)g_h2;

    for (int r = 0; r < TILE / 8; r++) {
        int local = w * (TILE / 8) + r;
        int node = base + local;
        if (node >= N) break;
        int s0 = __ldg(&g_rowptr[node]), s1 = __ldg(&g_rowptr[node + 1]);
        float4 agg = gather_f4(h2f4, s0, s1, slot, q);
        if (slot == 0) {
            float inv = 1.0f / fmaxf((float)(s1 - s0), 1.0f);
            agg.x *= inv; agg.y *= inv; agg.z *= inv; agg.w *= inv;
            *(float4*)&sA[local * SROW + q * 4] = agg;
            *(float4*)&sH[local * SROW + q * 4] = __ldg(&h2f4[node * 8 + q]);
        }
    }
    __syncthreads();

    int tq = threadIdx.x & 7, tg = threadIdx.x >> 3;
    int n0 = tg * 4;
    float4 c0 = sb4[tq], c1 = c0, c2 = c0, c3 = c0;
    #pragma unroll 4
    for (int k = 0; k < 32; k++) {
        float4 wl = sWl4[k * 8 + tq];
        float4 wr = sWr4[k * 8 + tq];
        float a0 = sA[(n0 + 0) * SROW + k], h0 = sH[(n0 + 0) * SROW + k];
        float a1 = sA[(n0 + 1) * SROW + k], h1 = sH[(n0 + 1) * SROW + k];
        float a2 = sA[(n0 + 2) * SROW + k], h2 = sH[(n0 + 2) * SROW + k];
        float a3 = sA[(n0 + 3) * SROW + k], h3 = sH[(n0 + 3) * SROW + k];
        c0.x += a0 * wl.x + h0 * wr.x; c0.y += a0 * wl.y + h0 * wr.y;
        c0.z += a0 * wl.z + h0 * wr.z; c0.w += a0 * wl.w + h0 * wr.w;
        c1.x += a1 * wl.x + h1 * wr.x; c1.y += a1 * wl.y + h1 * wr.y;
        c1.z += a1 * wl.z + h1 * wr.z; c1.w += a1 * wl.w + h1 * wr.w;
        c2.x += a2 * wl.x + h2 * wr.x; c2.y += a2 * wl.y + h2 * wr.y;
        c2.z += a2 * wl.z + h2 * wr.z; c2.w += a2 * wl.w + h2 * wr.w;
        c3.x += a3 * wl.x + h3 * wr.x; c3.y += a3 * wl.y + h3 * wr.y;
        c3.z += a3 * wl.z + h3 * wr.z; c3.w += a3 * wl.w + h3 * wr.w;
    }
    float4* h3f4 = (float4*)g_h1;   // reuse h1 buffer for h3
    int nb = base + n0;
    if (nb + 0 < N) h3f4[(nb + 0) * 8 + tq] = lrelu4(c0);
    if (nb + 1 < N) h3f4[(nb + 1) * 8 + tq] = lrelu4(c1);
    if (nb + 2 < N) h3f4[(nb + 2) * 8 + tq] = lrelu4(c2);
    if (nb + 3 < N) h3f4[(nb + 3) * 8 + tq] = lrelu4(c3);
}

// ---------------------------------------------------------------------------
// 6) Dense up-projection + FUSED tri-pooling. Tile of 128 contiguous nodes.
//    Register pool accumulators flushed at graph boundaries (batch sorted).
// ---------------------------------------------------------------------------
#define SROW3 36
__device__ __forceinline__ void flush_pool4(int g, int cbase, float4 ps, float4 pm) {
    if (g < 0) return;
    float* sp = g_gsum + g * 128 + cbase;
    unsigned* mp = g_gmax + g * 128 + cbase;
    atomicAdd(sp + 0, ps.x); atomicAdd(sp + 1, ps.y);
    atomicAdd(sp + 2, ps.z); atomicAdd(sp + 3, ps.w);
    atomicMax(mp + 0, fenc(pm.x)); atomicMax(mp + 1, fenc(pm.y));
    atomicMax(mp + 2, fenc(pm.z)); atomicMax(mp + 3, fenc(pm.w));
}

__global__ __launch_bounds__(256, 4)
void k_upproj_pool(const float* __restrict__ Wu, const float* __restrict__ bu,
                   const void* __restrict__ batch, int N, int bbase) {
    __shared__ float sh3[TILE * SROW3];
    __shared__ float4 sWu4[1024];       // Wu [32][128] = 16 KB
    __shared__ float4 sbu4[32];
    __shared__ int sb64;
    for (int i = threadIdx.x; i < 1024; i += 256)
        sWu4[i] = __ldg(&((const float4*)Wu)[i]);
    if (threadIdx.x < 32) {
        sbu4[threadIdx.x] = __ldg(&((const float4*)bu)[threadIdx.x]);
        int f = sniff64((const unsigned*)batch, bbase);
        if (threadIdx.x == 0) sb64 = f;
    }

    int base = blockIdx.x * TILE;
    const float4* h3f4 = (const float4*)g_h1;
    for (int i = threadIdx.x; i < TILE * 8; i += 256) {
        int local = i >> 3, q = i & 7;
        int node = base + local;
        int nc = (node < N) ? node : (N - 1);
        *(float4*)&sh3[local * SROW3 + q * 4] = __ldg(&h3f4[nc * 8 + q]);
    }
    __syncthreads();
    int e64 = sb64;

    int oq = threadIdx.x & 31, g8 = threadIdx.x >> 5;
    int cbase = oq * 4;
    int gcur = -1;
    float4 psum = make_float4(0.f, 0.f, 0.f, 0.f);
    float4 pmax = make_float4(-INFINITY, -INFINITY, -INFINITY, -INFINITY);

    #pragma unroll
    for (int pass = 0; pass < 4; pass++) {
        int nb = pass * 32 + g8 * 4;
        float4 u0 = sbu4[oq], u1 = u0, u2 = u0, u3 = u0;
        #pragma unroll 4
        for (int k = 0; k < 32; k++) {
            float4 wv = sWu4[k * 32 + oq];
            float p0 = sh3[(nb + 0) * SROW3 + k];
            float p1 = sh3[(nb + 1) * SROW3 + k];
            float p2 = sh3[(nb + 2) * SROW3 + k];
            float p3 = sh3[(nb + 3) * SROW3 + k];
            u0.x += p0 * wv.x; u0.y += p0 * wv.y; u0.z += p0 * wv.z; u0.w += p0 * wv.w;
            u1.x += p1 * wv.x; u1.y += p1 * wv.y; u1.z += p1 * wv.z; u1.w += p1 * wv.w;
            u2.x += p2 * wv.x; u2.y += p2 * wv.y; u2.z += p2 * wv.z; u2.w += p2 * wv.w;
            u3.x += p3 * wv.x; u3.y += p3 * wv.y; u3.z += p3 * wv.z; u3.w += p3 * wv.w;
        }
        float4 hu[4] = { lrelu4(u0), lrelu4(u1), lrelu4(u2), lrelu4(u3) };
        #pragma unroll
        for (int j = 0; j < 4; j++) {
            int node = base + nb + j;
            if (node >= N) break;
            int gid = e64 ? (int)((const long long*)batch)[node]
                          : ((const int*)batch)[node];
            if (gid != gcur) {
                flush_pool4(gcur, cbase, psum, pmax);
                gcur = gid;
                psum = make_float4(0.f, 0.f, 0.f, 0.f);
                pmax = make_float4(-INFINITY, -INFINITY, -INFINITY, -INFINITY);
            }
            float4 v = hu[j];
            psum.x += v.x; psum.y += v.y; psum.z += v.z; psum.w += v.w;
            pmax.x = fmaxf(pmax.x, v.x); pmax.y = fmaxf(pmax.y, v.y);
            pmax.z = fmaxf(pmax.z, v.z); pmax.w = fmaxf(pmax.w, v.w);
        }
    }
    flush_pool4(gcur, cbase, psum, pmax);
}

// ---------------------------------------------------------------------------
// 7) Head + replay-state reset.
// ---------------------------------------------------------------------------
__global__ void k_head(const float* __restrict__ Wf1, const float* __restrict__ bf1,
                       const float* __restrict__ Wf2, const float* __restrict__ bf2,
                       float* __restrict__ out, int N, int G) {
    __shared__ float sz[384], sz2[128];
    int g = blockIdx.x;
    int c = threadIdx.x;   // 128 threads
    float sum = g_gsum[g * 128 + c];
    float mx  = fdec(g_gmax[g * 128 + c]);
    float cnt = (float)(g_start[g + 1] - g_start[g]);
    sz[c]       = sum / fmaxf(cnt, 1.0f);
    sz[128 + c] = mx;
    sz[256 + c] = sum;
    __syncthreads();
    // Replay-state reset (none of these are read by k_head after this point).
    g_gsum[g * 128 + c] = 0.f;
    g_gmax[g * 128 + c] = FENC_NEG_INF;
    for (int i = g * 128 + c; i < N; i += G * 128) g_aggcnt[i] = make_float2(0.f, 0.f);

    float acc = bf1[c];
    #pragma unroll 4
    for (int k = 0; k < 384; k++) acc += sz[k] * Wf1[k * 128 + c];
    sz2[c] = lrelu(acc);
    __syncthreads();
    if (c < 51) {
        float o = bf2[c];
        #pragma unroll 4
        for (int k = 0; k < 128; k++) o += sz2[k] * Wf2[k * 51 + c];
        out[g * 51 + c] = o;
    }
}

// ---------------------------------------------------------------------------
extern "C" void kernel_launch(void* const* d_in, const int* in_sizes, int n_in,
                              void* d_out, int out_size) {
    const float* x    = (const float*)d_in[0];
    const void*  eidx = d_in[1];
    const void*  batch= d_in[2];
    const float* W1l  = (const float*)d_in[3];
    const float* b1   = (const float*)d_in[4];
    const float* W1r  = (const float*)d_in[5];
    const float* W2l  = (const float*)d_in[6];
    const float* b2   = (const float*)d_in[7];
    const float* W2r  = (const float*)d_in[8];
    const float* W3l  = (const float*)d_in[9];
    const float* b3   = (const float*)d_in[10];
    const float* W3r  = (const float*)d_in[11];
    const float* Wu   = (const float*)d_in[12];
    const float* bu   = (const float*)d_in[13];
    const float* Wf1  = (const float*)d_in[14];
    const float* bf1  = (const float*)d_in[15];
    const float* Wf2  = (const float*)d_in[16];
    const float* bf2  = (const float*)d_in[17];
    float* out = (float*)d_out;

    int N = in_sizes[0];
    int E = in_sizes[1] / 2;
    int G = out_size / 51;
    int bbase = (N - 64) & ~1;

    int fill_threads = (E > N * 8) ? E : N * 8;
    int tile_blocks = (N + TILE - 1) / TILE;
    int starts_blocks = 1 + (N + 1023) / 1024;

    k_hist<<<(E + 255) / 256, 256>>>(x, eidx, E);
    k_scan_starts<<<starts_blocks, 1024>>>(batch, N, E, G, bbase);
    k_csrfill_l1<<<(fill_threads + 255) / 256, 256>>>(eidx, x, W1l, b1, W1r, E, N);
    k_sage2<<<tile_blocks, 256>>>(W2l, b2, W2r, N);        // <- profiled launch #4
    k_sage3<<<tile_blocks, 256>>>(W3l, b3, W3r, N);
    k_upproj_pool<<<tile_blocks, 256>>>(Wu, bu, batch, N, bbase);
    k_head<<<G, 128>>>(Wf1, bf1, Wf2, bf2, out, N, G);
}

// round 17
// speedup vs baseline: 1.3230x; 1.0129x over previous
#include <cuda_runtime.h>
#include <cuda_bf16.h>
#include <math.h>

// ----------------------------------------------------------------------------
// GraphSAGE (3 layers) + up-proj + FUSED tri-pooling + MLP head. 6 launches.
// R16 + grid-stride even-wave sage kernels + sage3/upproj/pool fusion
// (R9-style smem reuse: h3 tile -> sA, Wu -> sH storage). h3/h4 never hit DRAM.
// N=100000, E=1600000, G=256, H=32, UP=128, out 51.
// Replay-safe: g_aggcnt / g_gsum / g_gmax reset by k_head tail.
// ----------------------------------------------------------------------------

#define MAXN 100000
#define MAXE 1600000
#define MAXG 256
#define TILE 128
#define SROW 36     // padded smem row stride (multiple of 4 for float4 align)
#define FENC_NEG_INF 0x007FFFFFu
#define SAGE2_BLOCKS 592   // 148 SMs x 4 resident -> even waves
#define SAGE3_BLOCKS 444   // 148 SMs x 3 resident -> even waves

__device__ int      g_csr[MAXE];
__device__ float2   g_aggcnt[MAXN];     // (.x = sum x[src], .y = in-degree) pre-zeroed
__device__ int      g_rowptr[MAXN + 1];
__device__ int      g_cursor[MAXN];
__device__ float    g_h1[MAXN * 32];
__device__ float    g_h2[MAXN * 32];
__device__ int      g_start[MAXG + 1];
__device__ float    g_gsum[MAXG * 128]; // per-graph channel sums (pre-zeroed)
__device__ unsigned g_gmax[MAXG * 128]; // encoded per-graph maxima (pre-zeroed)

__device__ __forceinline__ float lrelu(float v) { return v > 0.f ? v : 0.01f * v; }
__device__ __forceinline__ float4 lrelu4(float4 v) {
    return make_float4(lrelu(v.x), lrelu(v.y), lrelu(v.z), lrelu(v.w));
}

__device__ __forceinline__ unsigned fenc(float f) {
    unsigned b = __float_as_uint(f);
    return (b & 0x80000000u) ? ~b : (b | 0x80000000u);
}
__device__ __forceinline__ float fdec(unsigned u) {
    return (u & 0x80000000u) ? __uint_as_float(u & 0x7FFFFFFFu)
                             : __uint_as_float(~u);
}

// Per-block dtype sniff: int64 little-endian small nonneg => odd words zero.
__device__ __forceinline__ int sniff64(const unsigned* w, int base) {
    int lane = threadIdx.x & 31;
    unsigned v = w[base + 2 * lane + 1];
    unsigned nz = __ballot_sync(0xffffffffu, v != 0u);
    return nz == 0u;
}

// ---------------------------------------------------------------------------
// 1) Histogram + layer-1 scalar scatter fused into ONE v2 float RED per edge.
// ---------------------------------------------------------------------------
__global__ void k_hist(const float* __restrict__ x, const void* __restrict__ eidx,
                       int E) {
    __shared__ int se64;
    if (threadIdx.x < 32) {
        int f = sniff64((const unsigned*)eidx, 0);
        if (threadIdx.x == 0) se64 = f;
    }
    __syncthreads();
    int i = blockIdx.x * blockDim.x + threadIdx.x;
    if (i >= E) return;
    int s, d;
    if (se64) {
        const long long* p = (const long long*)eidx;
        s = (int)p[i];
        d = (int)p[(size_t)E + i];
    } else {
        const int* p = (const int*)eidx;
        s = p[i];
        d = p[E + i];
    }
    float xv = __ldg(&x[s]);
    float* addr = (float*)&g_aggcnt[d];
    asm volatile("red.global.add.v2.f32 [%0], {%1,%2};"
                 :: "l"(addr), "f"(xv), "f"(1.0f) : "memory");
}

// ---------------------------------------------------------------------------
// 2) Scan + starts in one launch. Block 0: single-block chunked exclusive scan.
//    Blocks >= 1: per-graph start offsets from sorted batch.
// ---------------------------------------------------------------------------
__global__ void k_scan_starts(const void* __restrict__ batch,
                              int N, int E, int G, int bbase) {
    if (blockIdx.x == 0) {
        __shared__ int ssum[1024];
        int t = threadIdx.x;
        int chunk = (N + 1023) / 1024;
        int a = t * chunk;
        int b = min(N, a + chunk);
        int s = 0;
        for (int i = a; i < b; i++) s += (int)g_aggcnt[i].y;
        ssum[t] = s;
        __syncthreads();
        for (int off = 1; off < 1024; off <<= 1) {
            int u = (t >= off) ? ssum[t - off] : 0;
            __syncthreads();
            ssum[t] += u;
            __syncthreads();
        }
        int run = ssum[t] - s;
        for (int i = a; i < b; i++) {
            g_rowptr[i] = run;
            g_cursor[i] = run;
            run += (int)g_aggcnt[i].y;
        }
        if (t == 1023) g_rowptr[N] = E;
    } else {
        __shared__ int sb64;
        if (threadIdx.x < 32) {
            int f = sniff64((const unsigned*)batch, bbase);
            if (threadIdx.x == 0) sb64 = f;
        }
        __syncthreads();
        int i = (blockIdx.x - 1) * blockDim.x + threadIdx.x;
        if (i >= N) return;
        long long bi, bp;
        if (sb64) {
            const long long* p = (const long long*)batch;
            bi = p[i]; bp = (i == 0) ? -1LL : p[i - 1];
        } else {
            const int* p = (const int*)batch;
            bi = p[i]; bp = (i == 0) ? -1LL : p[i - 1];
        }
        if (bi != bp) for (long long g = bp + 1; g <= bi; g++) g_start[g] = i;
        if (i == N - 1) for (long long g = bi + 1; g <= G; g++) g_start[g] = N;
    }
}

// ---------------------------------------------------------------------------
// 3) CSR fill + fused layer-1 transform (independent work ranges).
// ---------------------------------------------------------------------------
__global__ void k_csrfill_l1(const void* __restrict__ eidx, const float* __restrict__ x,
                             const float* __restrict__ W1l, const float* __restrict__ b1,
                             const float* __restrict__ W1r, int E, int N) {
    __shared__ int se64;
    if (threadIdx.x < 32) {
        int f = sniff64((const unsigned*)eidx, 0);
        if (threadIdx.x == 0) se64 = f;
    }
    __syncthreads();
    int i = blockIdx.x * blockDim.x + threadIdx.x;
    if (i < E) {
        int s, d;
        if (se64) {
            const long long* p = (const long long*)eidx;
            s = (int)p[i];
            d = (int)p[(size_t)E + i];
        } else {
            const int* p = (const int*)eidx;
            s = p[i];
            d = p[E + i];
        }
        int pos = atomicAdd(&g_cursor[d], 1);
        g_csr[pos] = s;
    }
    if (i < N * 8) {
        int node = i >> 3, q = i & 7;
        float a  = __ldg(&((const float*)g_aggcnt)[node * 2]);
        float xv = __ldg(&x[node]);
        float4 wl = __ldg(&((const float4*)W1l)[q]);
        float4 wr = __ldg(&((const float4*)W1r)[q]);
        float4 bb = __ldg(&((const float4*)b1)[q]);
        float4 o;
        o.x = lrelu(a * wl.x + xv * wr.x + bb.x);
        o.y = lrelu(a * wl.y + xv * wr.y + bb.y);
        o.z = lrelu(a * wl.z + xv * wr.z + bb.z);
        o.w = lrelu(a * wl.w + xv * wr.w + bb.w);
        ((float4*)g_h1)[node * 8 + q] = o;
    }
}

// ---------------------------------------------------------------------------
// Gather helper: warp gathers 32-ch sum into float4 (quad q). 4 edge slots x
// 4-deep unroll => 4 independent (csr,row) pairs in flight per lane (MLP 4).
// ---------------------------------------------------------------------------
__device__ __forceinline__ float4 gather_f4(const float4* __restrict__ hf4,
                                            int s0, int s1, int slot, int q) {
    float4 a0 = make_float4(0.f, 0.f, 0.f, 0.f);
    float4 a1 = a0, a2 = a0, a3 = a0;
    int e = s0 + slot;
    for (; e + 12 < s1; e += 16) {
        int i0 = __ldg(&g_csr[e]);
        int i1 = __ldg(&g_csr[e + 4]);
        int i2 = __ldg(&g_csr[e + 8]);
        int i3 = __ldg(&g_csr[e + 12]);
        float4 v0 = __ldg(&hf4[i0 * 8 + q]);
        float4 v1 = __ldg(&hf4[i1 * 8 + q]);
        float4 v2 = __ldg(&hf4[i2 * 8 + q]);
        float4 v3 = __ldg(&hf4[i3 * 8 + q]);
        a0.x += v0.x; a0.y += v0.y; a0.z += v0.z; a0.w += v0.w;
        a1.x += v1.x; a1.y += v1.y; a1.z += v1.z; a1.w += v1.w;
        a2.x += v2.x; a2.y += v2.y; a2.z += v2.z; a2.w += v2.w;
        a3.x += v3.x; a3.y += v3.y; a3.z += v3.z; a3.w += v3.w;
    }
    for (; e < s1; e += 4) {
        int i0 = __ldg(&g_csr[e]);
        float4 v0 = __ldg(&hf4[i0 * 8 + q]);
        a0.x += v0.x; a0.y += v0.y; a0.z += v0.z; a0.w += v0.w;
    }
    float4 acc;
    acc.x = (a0.x + a1.x) + (a2.x + a3.x);
    acc.y = (a0.y + a1.y) + (a2.y + a3.y);
    acc.z = (a0.z + a1.z) + (a2.z + a3.z);
    acc.w = (a0.w + a1.w) + (a2.w + a3.w);
    #pragma unroll
    for (int off = 8; off <= 16; off <<= 1) {
        acc.x += __shfl_xor_sync(0xffffffffu, acc.x, off);
        acc.y += __shfl_xor_sync(0xffffffffu, acc.y, off);
        acc.z += __shfl_xor_sync(0xffffffffu, acc.z, off);
        acc.w += __shfl_xor_sync(0xffffffffu, acc.w, off);
    }
    return acc;
}

// ---------------------------------------------------------------------------
// 4) Layer 2: grid-stride over 128-node tiles (even waves). Gather -> smem,
//    tiled GEMM: h2 = lrelu(agg@W2l + b2 + h1@W2r).
// ---------------------------------------------------------------------------
__global__ __launch_bounds__(256, 4)
void k_sage2(const float* __restrict__ Wl, const float* __restrict__ b,
             const float* __restrict__ Wr, int N, int ntiles) {
    __shared__ float sA[TILE * SROW], sH[TILE * SROW];
    __shared__ float4 sWl4[256], sWr4[256], sb4[8];
    if (threadIdx.x < 256) {
        sWl4[threadIdx.x] = __ldg(&((const float4*)Wl)[threadIdx.x]);
        sWr4[threadIdx.x] = __ldg(&((const float4*)Wr)[threadIdx.x]);
    }
    if (threadIdx.x < 8) sb4[threadIdx.x] = __ldg(&((const float4*)b)[threadIdx.x]);

    int lane = threadIdx.x & 31, w = threadIdx.x >> 5;
    int slot = lane >> 3, q = lane & 7;
    int tq = threadIdx.x & 7, tg = threadIdx.x >> 3;
    const float4* h1f4 = (const float4*)g_h1;
    float4* h2f4 = (float4*)g_h2;

    for (int tile = blockIdx.x; tile < ntiles; tile += gridDim.x) {
        int base = tile * TILE;
        for (int r = 0; r < TILE / 8; r++) {
            int local = w * (TILE / 8) + r;
            int node = base + local;
            if (node >= N) break;
            int s0 = __ldg(&g_rowptr[node]), s1 = __ldg(&g_rowptr[node + 1]);
            float4 agg = gather_f4(h1f4, s0, s1, slot, q);
            if (slot == 0) {
                *(float4*)&sA[local * SROW + q * 4] = agg;
                *(float4*)&sH[local * SROW + q * 4] = __ldg(&h1f4[node * 8 + q]);
            }
        }
        __syncthreads();

        int n0 = tg * 4;
        float4 c0 = sb4[tq], c1 = c0, c2 = c0, c3 = c0;
        #pragma unroll 4
        for (int k = 0; k < 32; k++) {
            float4 wl = sWl4[k * 8 + tq];
            float4 wr = sWr4[k * 8 + tq];
            float a0 = sA[(n0 + 0) * SROW + k], h0 = sH[(n0 + 0) * SROW + k];
            float a1 = sA[(n0 + 1) * SROW + k], h1 = sH[(n0 + 1) * SROW + k];
            float a2 = sA[(n0 + 2) * SROW + k], h2 = sH[(n0 + 2) * SROW + k];
            float a3 = sA[(n0 + 3) * SROW + k], h3 = sH[(n0 + 3) * SROW + k];
            c0.x += a0 * wl.x + h0 * wr.x; c0.y += a0 * wl.y + h0 * wr.y;
            c0.z += a0 * wl.z + h0 * wr.z; c0.w += a0 * wl.w + h0 * wr.w;
            c1.x += a1 * wl.x + h1 * wr.x; c1.y += a1 * wl.y + h1 * wr.y;
            c1.z += a1 * wl.z + h1 * wr.z; c1.w += a1 * wl.w + h1 * wr.w;
            c2.x += a2 * wl.x + h2 * wr.x; c2.y += a2 * wl.y + h2 * wr.y;
            c2.z += a2 * wl.z + h2 * wr.z; c2.w += a2 * wl.w + h2 * wr.w;
            c3.x += a3 * wl.x + h3 * wr.x; c3.y += a3 * wl.y + h3 * wr.y;
            c3.z += a3 * wl.z + h3 * wr.z; c3.w += a3 * wl.w + h3 * wr.w;
        }
        int nb = base + n0;
        if (nb + 0 < N) h2f4[(nb + 0) * 8 + tq] = lrelu4(c0);
        if (nb + 1 < N) h2f4[(nb + 1) * 8 + tq] = lrelu4(c1);
        if (nb + 2 < N) h2f4[(nb + 2) * 8 + tq] = lrelu4(c2);
        if (nb + 3 < N) h2f4[(nb + 3) * 8 + tq] = lrelu4(c3);
        __syncthreads();   // protect sA/sH before next tile's gather
    }
}

// ---------------------------------------------------------------------------
// 5) Layer 3 (mean) + up-proj + FUSED pooling, grid-stride tiles.
//    Phases per tile: gather->smem | GEMM h3 | h3->sA, Wu->sH storage |
//    upproj from smem + register pooling, flush at graph boundaries.
// ---------------------------------------------------------------------------
__device__ __forceinline__ void flush_pool4(int g, int cbase, float4 ps, float4 pm) {
    if (g < 0) return;
    float* sp = g_gsum + g * 128 + cbase;
    unsigned* mp = g_gmax + g * 128 + cbase;
    atomicAdd(sp + 0, ps.x); atomicAdd(sp + 1, ps.y);
    atomicAdd(sp + 2, ps.z); atomicAdd(sp + 3, ps.w);
    atomicMax(mp + 0, fenc(pm.x)); atomicMax(mp + 1, fenc(pm.y));
    atomicMax(mp + 2, fenc(pm.z)); atomicMax(mp + 3, fenc(pm.w));
}

__global__ __launch_bounds__(256, 3)
void k_sage3_pool(const float* __restrict__ Wl, const float* __restrict__ b,
                  const float* __restrict__ Wr, const float* __restrict__ Wu,
                  const float* __restrict__ bu, const void* __restrict__ batch,
                  int N, int ntiles, int bbase) {
    __shared__ float sA[TILE * SROW], sH[TILE * SROW];
    __shared__ float4 sWl4[256], sWr4[256], sb4[8], sbu4[32];
    __shared__ int sb64;
    if (threadIdx.x < 256) {
        sWl4[threadIdx.x] = __ldg(&((const float4*)Wl)[threadIdx.x]);
        sWr4[threadIdx.x] = __ldg(&((const float4*)Wr)[threadIdx.x]);
    }
    if (threadIdx.x < 8)  sb4[threadIdx.x]  = __ldg(&((const float4*)b)[threadIdx.x]);
    if (threadIdx.x < 32) {
        sbu4[threadIdx.x] = __ldg(&((const float4*)bu)[threadIdx.x]);
        int f = sniff64((const unsigned*)batch, bbase);
        if (threadIdx.x == 0) sb64 = f;
    }
    __syncthreads();
    int e64 = sb64;

    int lane = threadIdx.x & 31, w = threadIdx.x >> 5;
    int slot = lane >> 3, q = lane & 7;
    int tq = threadIdx.x & 7, tg = threadIdx.x >> 3;
    int oq = threadIdx.x & 31, g8 = threadIdx.x >> 5;
    int cbase = oq * 4;
    const float4* h2f4 = (const float4*)g_h2;
    float4* sWu4 = (float4*)sH;    // Wu staged into sH's storage per tile

    for (int tile = blockIdx.x; tile < ntiles; tile += gridDim.x) {
        int base = tile * TILE;
        // --- gather phase ---
        for (int r = 0; r < TILE / 8; r++) {
            int local = w * (TILE / 8) + r;
            int node = base + local;
            if (node >= N) break;
            int s0 = __ldg(&g_rowptr[node]), s1 = __ldg(&g_rowptr[node + 1]);
            float4 agg = gather_f4(h2f4, s0, s1, slot, q);
            if (slot == 0) {
                float inv = 1.0f / fmaxf((float)(s1 - s0), 1.0f);
                agg.x *= inv; agg.y *= inv; agg.z *= inv; agg.w *= inv;
                *(float4*)&sA[local * SROW + q * 4] = agg;
                *(float4*)&sH[local * SROW + q * 4] = __ldg(&h2f4[node * 8 + q]);
            }
        }
        __syncthreads();

        // --- GEMM: h3 = lrelu(agg@W3l + b3 + h2@W3r), 4 nodes x 4 ch ---
        int n0 = tg * 4;
        float4 c0 = sb4[tq], c1 = c0, c2 = c0, c3 = c0;
        #pragma unroll 4
        for (int k = 0; k < 32; k++) {
            float4 wl = sWl4[k * 8 + tq];
            float4 wr = sWr4[k * 8 + tq];
            float a0 = sA[(n0 + 0) * SROW + k], h0 = sH[(n0 + 0) * SROW + k];
            float a1 = sA[(n0 + 1) * SROW + k], h1 = sH[(n0 + 1) * SROW + k];
            float a2 = sA[(n0 + 2) * SROW + k], h2 = sH[(n0 + 2) * SROW + k];
            float a3 = sA[(n0 + 3) * SROW + k], h3 = sH[(n0 + 3) * SROW + k];
            c0.x += a0 * wl.x + h0 * wr.x; c0.y += a0 * wl.y + h0 * wr.y;
            c0.z += a0 * wl.z + h0 * wr.z; c0.w += a0 * wl.w + h0 * wr.w;
            c1.x += a1 * wl.x + h1 * wr.x; c1.y += a1 * wl.y + h1 * wr.y;
            c1.z += a1 * wl.z + h1 * wr.z; c1.w += a1 * wl.w + h1 * wr.w;
            c2.x += a2 * wl.x + h2 * wr.x; c2.y += a2 * wl.y + h2 * wr.y;
            c2.z += a2 * wl.z + h2 * wr.z; c2.w += a2 * wl.w + h2 * wr.w;
            c3.x += a3 * wl.x + h3 * wr.x; c3.y += a3 * wl.y + h3 * wr.y;
            c3.z += a3 * wl.z + h3 * wr.z; c3.w += a3 * wl.w + h3 * wr.w;
        }
        __syncthreads();   // all reads of sA/sH done

        // --- stage: h3 tile -> sA, Wu -> sH storage ---
        *(float4*)&sA[(n0 + 0) * SROW + tq * 4] = lrelu4(c0);
        *(float4*)&sA[(n0 + 1) * SROW + tq * 4] = lrelu4(c1);
        *(float4*)&sA[(n0 + 2) * SROW + tq * 4] = lrelu4(c2);
        *(float4*)&sA[(n0 + 3) * SROW + tq * 4] = lrelu4(c3);
        #pragma unroll
        for (int i = threadIdx.x; i < 1024; i += 256)
            sWu4[i] = __ldg(&((const float4*)Wu)[i]);
        __syncthreads();

        // --- up-proj + register pooling ---
        int gcur = -1;
        float4 psum = make_float4(0.f, 0.f, 0.f, 0.f);
        float4 pmax = make_float4(-INFINITY, -INFINITY, -INFINITY, -INFINITY);
        #pragma unroll
        for (int pass = 0; pass < 4; pass++) {
            int nb = pass * 32 + g8 * 4;
            float4 u0 = sbu4[oq], u1 = u0, u2 = u0, u3 = u0;
            #pragma unroll 4
            for (int k = 0; k < 32; k++) {
                float4 wv = sWu4[k * 32 + oq];
                float p0 = sA[(nb + 0) * SROW + k];
                float p1 = sA[(nb + 1) * SROW + k];
                float p2 = sA[(nb + 2) * SROW + k];
                float p3 = sA[(nb + 3) * SROW + k];
                u0.x += p0 * wv.x; u0.y += p0 * wv.y; u0.z += p0 * wv.z; u0.w += p0 * wv.w;
                u1.x += p1 * wv.x; u1.y += p1 * wv.y; u1.z += p1 * wv.z; u1.w += p1 * wv.w;
                u2.x += p2 * wv.x; u2.y += p2 * wv.y; u2.z += p2 * wv.z; u2.w += p2 * wv.w;
                u3.x += p3 * wv.x; u3.y += p3 * wv.y; u3.z += p3 * wv.z; u3.w += p3 * wv.w;
            }
            float4 hu[4] = { lrelu4(u0), lrelu4(u1), lrelu4(u2), lrelu4(u3) };
            #pragma unroll
            for (int j = 0; j < 4; j++) {
                int node = base + nb + j;
                if (node >= N) break;
                int gid = e64 ? (int)((const long long*)batch)[node]
                              : ((const int*)batch)[node];
                if (gid != gcur) {
                    flush_pool4(gcur, cbase, psum, pmax);
                    gcur = gid;
                    psum = make_float4(0.f, 0.f, 0.f, 0.f);
                    pmax = make_float4(-INFINITY, -INFINITY, -INFINITY, -INFINITY);
                }
                float4 v = hu[j];
                psum.x += v.x; psum.y += v.y; psum.z += v.z; psum.w += v.w;
                pmax.x = fmaxf(pmax.x, v.x); pmax.y = fmaxf(pmax.y, v.y);
                pmax.z = fmaxf(pmax.z, v.z); pmax.w = fmaxf(pmax.w, v.w);
            }
        }
        flush_pool4(gcur, cbase, psum, pmax);
        __syncthreads();   // protect sA/sH(Wu) before next tile's gather
    }
}

// ---------------------------------------------------------------------------
// 6) Head + replay-state reset.
// ---------------------------------------------------------------------------
__global__ void k_head(const float* __restrict__ Wf1, const float* __restrict__ bf1,
                       const float* __restrict__ Wf2, const float* __restrict__ bf2,
                       float* __restrict__ out, int N, int G) {
    __shared__ float sz[384], sz2[128];
    int g = blockIdx.x;
    int c = threadIdx.x;   // 128 threads
    float sum = g_gsum[g * 128 + c];
    float mx  = fdec(g_gmax[g * 128 + c]);
    float cnt = (float)(g_start[g + 1] - g_start[g]);
    sz[c]       = sum / fmaxf(cnt, 1.0f);
    sz[128 + c] = mx;
    sz[256 + c] = sum;
    __syncthreads();
    g_gsum[g * 128 + c] = 0.f;
    g_gmax[g * 128 + c] = FENC_NEG_INF;
    for (int i = g * 128 + c; i < N; i += G * 128) g_aggcnt[i] = make_float2(0.f, 0.f);

    float acc = bf1[c];
    #pragma unroll 4
    for (int k = 0; k < 384; k++) acc += sz[k] * Wf1[k * 128 + c];
    sz2[c] = lrelu(acc);
    __syncthreads();
    if (c < 51) {
        float o = bf2[c];
        #pragma unroll 4
        for (int k = 0; k < 128; k++) o += sz2[k] * Wf2[k * 51 + c];
        out[g * 51 + c] = o;
    }
}

// ---------------------------------------------------------------------------
extern "C" void kernel_launch(void* const* d_in, const int* in_sizes, int n_in,
                              void* d_out, int out_size) {
    const float* x    = (const float*)d_in[0];
    const void*  eidx = d_in[1];
    const void*  batch= d_in[2];
    const float* W1l  = (const float*)d_in[3];
    const float* b1   = (const float*)d_in[4];
    const float* W1r  = (const float*)d_in[5];
    const float* W2l  = (const float*)d_in[6];
    const float* b2   = (const float*)d_in[7];
    const float* W2r  = (const float*)d_in[8];
    const float* W3l  = (const float*)d_in[9];
    const float* b3   = (const float*)d_in[10];
    const float* W3r  = (const float*)d_in[11];
    const float* Wu   = (const float*)d_in[12];
    const float* bu   = (const float*)d_in[13];
    const float* Wf1  = (const float*)d_in[14];
    const float* bf1  = (const float*)d_in[15];
    const float* Wf2  = (const float*)d_in[16];
    const float* bf2  = (const float*)d_in[17];
    float* out = (float*)d_out;

    int N = in_sizes[0];
    int E = in_sizes[1] / 2;
    int G = out_size / 51;
    int bbase = (N - 64) & ~1;

    int fill_threads = (E > N * 8) ? E : N * 8;
    int ntiles = (N + TILE - 1) / TILE;
    int starts_blocks = 1 + (N + 1023) / 1024;
    int s2_blocks = (ntiles < SAGE2_BLOCKS) ? ntiles : SAGE2_BLOCKS;
    int s3_blocks = (ntiles < SAGE3_BLOCKS) ? ntiles : SAGE3_BLOCKS;

    k_hist<<<(E + 255) / 256, 256>>>(x, eidx, E);
    k_scan_starts<<<starts_blocks, 1024>>>(batch, N, E, G, bbase);
    k_csrfill_l1<<<(fill_threads + 255) / 256, 256>>>(eidx, x, W1l, b1, W1r, E, N);
    k_sage2<<<s2_blocks, 256>>>(W2l, b2, W2r, N, ntiles);  // <- profiled launch #4
    k_sage3_pool<<<s3_blocks, 256>>>(W3l, b3, W3r, Wu, bu, batch, N, ntiles, bbase);
    k_head<<<G, 128>>>(Wf1, bf1, Wf2, bf2, out, N, G);
}